// round 6
// baseline (speedup 1.0000x reference)
#include <cuda_runtime.h>
#include <cstdint>

#define BB 8
#define SS 4096
#define DD 1024
#define MTOT (BB*SS)            // 32768
#define NELEM (MTOT*DD)
#define NK 1024

#define NCH 32
#define CHL 128                 // SS/NCH

// ---- GEMM tiling ----
#define TM 128
#define TN 128
#define TKC 32
#define KT (NK/TKC)             // 32
#define STAGES 3
#define TST 36                  // smem row stride (floats) for both A and B tiles
#define ABYT (TM*TST*4)         // 18432
#define BBYT (TN*TST*4)         // 18432
#define STBYT (ABYT+BBYT)       // 36864
#define SMEM_REQ (STAGES*STBYT) // 110592

// ---------------- scratch ----------------
__device__ float g_xg[NELEM];
__device__ float g_u [NELEM];
__device__ float g_v [NELEM];
__device__ float g_gx[NELEM];
__device__ float g_ga[NELEM];
__device__ float g_of[NELEM];
__device__ float g_wt[6*NK*NK];          // tf32-rounded, TRANSPOSED weights [N][K]
__device__ float g_end[BB*NCH*DD];
__device__ float g_P  [BB*NCH*DD];
__device__ float g_cr [BB*NCH*DD];

// ---------------- helpers ----------------
__device__ __forceinline__ float to_tf32(float x) {
    float r; asm("cvt.rna.tf32.f32 %0, %1;" : "=f"(r) : "f"(x)); return r;
}
__device__ __forceinline__ uint32_t smem_u32(const void* p) {
    uint32_t a;
    asm("{ .reg .u64 t; cvta.to.shared.u64 t, %1; cvt.u32.u64 %0, t; }" : "=r"(a) : "l"(p));
    return a;
}
__device__ __forceinline__ void cp16(uint32_t saddr, const void* gaddr) {
    asm volatile("cp.async.cg.shared.global [%0], [%1], 16;" :: "r"(saddr), "l"(gaddr));
}
__device__ __forceinline__ void cp_commit() {
    asm volatile("cp.async.commit_group;" ::: "memory");
}
__device__ __forceinline__ void cp_wait1() {
    asm volatile("cp.async.wait_group 1;" ::: "memory");
}
__device__ __forceinline__ void ldsm4(uint32_t* r, uint32_t addr) {
    asm volatile("ldmatrix.sync.aligned.m8n8.x4.shared.b16 {%0,%1,%2,%3}, [%4];"
        : "=r"(r[0]), "=r"(r[1]), "=r"(r[2]), "=r"(r[3]) : "r"(addr));
}
__device__ __forceinline__ void mma_tf32(float4& c, const uint32_t* a, uint32_t b0, uint32_t b1) {
    asm volatile(
        "mma.sync.aligned.m16n8k8.row.col.f32.tf32.tf32.f32 "
        "{%0,%1,%2,%3},{%4,%5,%6,%7},{%8,%9},{%0,%1,%2,%3};\n"
        : "+f"(c.x), "+f"(c.y), "+f"(c.z), "+f"(c.w)
        : "r"(a[0]), "r"(a[1]), "r"(a[2]), "r"(a[3]), "r"(b0), "r"(b1));
}

// ---------------- weight prep: transpose + round to tf32 ----------------
// dst[n*NK + k] = tf32(src[k*NK + n])
__global__ void transround_kernel(const float* __restrict__ src, float* __restrict__ dst) {
    __shared__ float tile[32][33];
    int x = blockIdx.x * 32 + threadIdx.x;   // n
    int y = blockIdx.y * 32 + threadIdx.y;   // k
#pragma unroll
    for (int j = 0; j < 32; j += 8)
        tile[threadIdx.y + j][threadIdx.x] = src[(size_t)(y + j) * NK + x];
    __syncthreads();
    x = blockIdx.y * 32 + threadIdx.x;       // k
    y = blockIdx.x * 32 + threadIdx.y;       // n
#pragma unroll
    for (int j = 0; j < 32; j += 8)
        dst[(size_t)(y + j) * NK + x] = to_tf32(tile[threadIdx.x][threadIdx.y + j]);
}

// ---------------- gelu (tanh approx), output rounded to tf32 ----------------
__global__ void gelu_kernel(const float* __restrict__ x, float* __restrict__ y) {
    int i = blockIdx.x * blockDim.x + threadIdx.x;
    float4 v = reinterpret_cast<const float4*>(x)[i];
    float* p = &v.x;
    float4 r; float* q = &r.x;
#pragma unroll
    for (int k = 0; k < 4; ++k) {
        float t = p[k];
        float inner = 0.7978845608028654f * (t + 0.044715f * t * t * t);
        q[k] = to_tf32(0.5f * t * (1.0f + tanhf(inner)));
    }
    reinterpret_cast<float4*>(y)[i] = r;
}

// ---------------- RG-LRU gate math ----------------
__global__ void gates_kernel(const float* __restrict__ v,
                             float* __restrict__ gx,
                             float* __restrict__ ga,
                             const float* __restrict__ a_param) {
    int i = blockIdx.x * blockDim.x + threadIdx.x;
    int d0 = (i * 4) & (DD - 1);
    float4 vv  = reinterpret_cast<const float4*>(v)[i];
    float4 gxx = reinterpret_cast<float4*>(gx)[i];
    float4 gaa = reinterpret_cast<float4*>(ga)[i];
    float4 ap  = *reinterpret_cast<const float4*>(&a_param[d0]);
    const float* pv = &vv.x; const float* pgx = &gxx.x;
    const float* pga = &gaa.x; const float* pap = &ap.x;
    float4 oa, os; float* pa = &oa.x; float* ps = &os.x;
#pragma unroll
    for (int k = 0; k < 4; ++k) {
        float sp = log1pf(expf(pap[k]));
        float la = -8.0f * pga[k] * sp;
        pa[k] = expf(la);
        ps[k] = sqrtf(1.0f - expf(2.0f * la)) * pgx[k] * pv[k];
    }
    reinterpret_cast<float4*>(ga)[i] = oa;
    reinterpret_cast<float4*>(gx)[i] = os;
}

// ---------------- chunked scans (3-pass) ----------------
__global__ void fwd_p1(const float* __restrict__ u, const float* __restrict__ a_fwd,
                       float* __restrict__ endv, float* __restrict__ Pv) {
    int d = threadIdx.x, bc = blockIdx.x;
    float a = a_fwd[d];
    size_t base = (size_t)bc * CHL * DD + d;
    float h = 0.f;
#pragma unroll 4
    for (int t = 0; t < CHL; ++t) h = fmaf(a, h, u[base + (size_t)t * DD]);
    float p = a;
#pragma unroll
    for (int i = 0; i < 7; ++i) p *= p;   // a^128
    endv[bc * DD + d] = h; Pv[bc * DD + d] = p;
}

__global__ void fwd_p2(const float* __restrict__ endv, const float* __restrict__ Pv,
                       float* __restrict__ cr) {
    int g = blockIdx.x * blockDim.x + threadIdx.x;
    int b = g >> 10, d = g & 1023;
    float acc = 0.f;
    for (int c = 0; c < NCH; ++c) {
        size_t i = (size_t)(b * NCH + c) * DD + d;
        cr[i] = acc;
        acc = endv[i] + Pv[i] * acc;
    }
}

__global__ void fwd_p3(float* __restrict__ u, const float* __restrict__ a_fwd,
                       const float* __restrict__ cr) {
    int d = threadIdx.x, bc = blockIdx.x;
    float a = a_fwd[d];
    size_t base = (size_t)bc * CHL * DD + d;
    float h = cr[bc * DD + d];
#pragma unroll 4
    for (int t = 0; t < CHL; ++t) {
        size_t i = base + (size_t)t * DD;
        h = fmaf(a, h, u[i]);
        u[i] = to_tf32(h);
    }
}

__global__ void bwd_p1(const float* __restrict__ s, const float* __restrict__ a,
                       float* __restrict__ endv, float* __restrict__ Pv) {
    int d = threadIdx.x, bc = blockIdx.x;
    size_t base = (size_t)bc * CHL * DD + d;
    float h = 0.f, p = 1.f;
#pragma unroll 4
    for (int t = CHL - 1; t >= 0; --t) {
        size_t i = base + (size_t)t * DD;
        float av = a[i];
        h = fmaf(av, h, s[i]);
        p *= av;
    }
    endv[bc * DD + d] = h; Pv[bc * DD + d] = p;
}

__global__ void bwd_p2(const float* __restrict__ endv, const float* __restrict__ Pv,
                       float* __restrict__ cr) {
    int g = blockIdx.x * blockDim.x + threadIdx.x;
    int b = g >> 10, d = g & 1023;
    float acc = 0.f;
    for (int c = NCH - 1; c >= 0; --c) {
        size_t i = (size_t)(b * NCH + c) * DD + d;
        cr[i] = acc;
        acc = endv[i] + Pv[i] * acc;
    }
}

__global__ void bwd_p3(float* __restrict__ s, const float* __restrict__ a,
                       const float* __restrict__ cr) {
    int d = threadIdx.x, bc = blockIdx.x;
    size_t base = (size_t)bc * CHL * DD + d;
    float h = cr[bc * DD + d];
#pragma unroll 4
    for (int t = CHL - 1; t >= 0; --t) {
        size_t i = base + (size_t)t * DD;
        h = fmaf(a[i], h, s[i]);
        s[i] = to_tf32(h);
    }
}

// ---------------- GEMM: C[M,N] = A[M,K] @ Wt[N,K]^T + bias ----------------
// A row-major [M,K]; Wt is pre-transposed weight [N,K] (both tf32-rounded).
// smem: A tile [128 rows][32 k] stride 36; B tile [128 n][32 k] stride 36.
// Fragments via ldmatrix.x4 (n-major B -> non-trans ldmatrix gives col-major frag).
// EPI: 0 = bias, 1 = sigmoid(acc+bias), 2 = acc+bias+add1+add2; ROUND: tf32 output
template <int EPI, int ROUND>
__global__ __launch_bounds__(256, 2)
void gemm_kernel(const float* __restrict__ A, const float* __restrict__ Wt,
                 const float* __restrict__ bias, float* __restrict__ C,
                 const float* __restrict__ add1, const float* __restrict__ add2) {
    extern __shared__ char sm[];
    const uint32_t smb = smem_u32(sm);

    const int tid  = threadIdx.x;
    const int wid  = tid >> 5;
    const int lane = tid & 31;
    const int wm   = wid & 3;       // warp M row (32 rows)
    const int wn   = wid >> 2;      // warp N col (64 cols)
    const int g    = lane >> 2;
    const int tg   = lane & 3;
    const int bm   = blockIdx.y;
    const int bn   = blockIdx.x;

    const float* Abase = A  + (size_t)(bm * TM) * NK;
    const float* Wbase = Wt + (size_t)(bn * TN) * NK;

    // cp.async slots: identical pattern for A and B (128 rows x 8 float4 of k)
    uint32_t sA[4], sB[4];
    const float* gA[4]; const float* gB[4];
#pragma unroll
    for (int it = 0; it < 4; ++it) {
        int p = tid + it * 256;
        int row = p >> 3, c4 = p & 7;
        sA[it] = (uint32_t)((row * TST + c4 * 4) * 4);
        sB[it] = (uint32_t)(ABYT + (row * TST + c4 * 4) * 4);
        gA[it] = Abase + (size_t)row * NK + c4 * 4;
        gB[it] = Wbase + (size_t)row * NK + c4 * 4;
    }

    auto issue = [&](int kt) {
        const uint32_t sb = smb + (kt % STAGES) * STBYT;
        const int ko = kt * TKC;
#pragma unroll
        for (int it = 0; it < 4; ++it) cp16(sb + sA[it], gA[it] + ko);
#pragma unroll
        for (int it = 0; it < 4; ++it) cp16(sb + sB[it], gB[it] + ko);
    };

    float4 acc[2][8];
#pragma unroll
    for (int i = 0; i < 2; ++i)
#pragma unroll
        for (int j = 0; j < 8; ++j) acc[i][j] = make_float4(0.f, 0.f, 0.f, 0.f);

    issue(0); cp_commit();
    issue(1); cp_commit();

    // ldmatrix per-lane base offsets (element units):
    // lanes 0-15 -> rows base+(lane&15), col +0; lanes 16-31 -> same rows, col +4
    const int lrow = lane & 15;
    const int lcol = (lane >> 4) * 4;
    const uint32_t aOff0 = (uint32_t)(((wm * 32 + lrow) * TST + lcol) * 4);          // i=0
    const uint32_t aOff1 = aOff0 + 16u * TST * 4u;                                   // i=1
    uint32_t bOff[4];
#pragma unroll
    for (int jp = 0; jp < 4; ++jp)
        bOff[jp] = (uint32_t)(ABYT + ((wn * 64 + jp * 16 + lrow) * TST + lcol) * 4);

    for (int kt = 0; kt < KT; ++kt) {
        cp_wait1();
        __syncthreads();
        if (kt + 2 < KT) issue(kt + 2);
        cp_commit();

        const uint32_t sb = smb + (kt % STAGES) * STBYT;

#pragma unroll
        for (int kk = 0; kk < TKC; kk += 8) {
            uint32_t af[2][4], bf[4][4];
            ldsm4(af[0], sb + aOff0 + kk * 4);
            ldsm4(af[1], sb + aOff1 + kk * 4);
#pragma unroll
            for (int jp = 0; jp < 4; ++jp) ldsm4(bf[jp], sb + bOff[jp] + kk * 4);
#pragma unroll
            for (int i = 0; i < 2; ++i) {
#pragma unroll
                for (int jp = 0; jp < 4; ++jp) {
                    mma_tf32(acc[i][jp * 2 + 0], af[i], bf[jp][0], bf[jp][2]);
                    mma_tf32(acc[i][jp * 2 + 1], af[i], bf[jp][1], bf[jp][3]);
                }
            }
        }
        __syncthreads();
    }

    // epilogue
#pragma unroll
    for (int i = 0; i < 2; ++i) {
        int row = bm * TM + wm * 32 + i * 16 + g;
#pragma unroll
        for (int j = 0; j < 8; ++j) {
            int col = bn * TN + wn * 64 + j * 8 + tg * 2;
            float b0 = bias[col], b1 = bias[col + 1];
            float v0 = acc[i][j].x + b0;
            float v1 = acc[i][j].y + b1;
            float v2 = acc[i][j].z + b0;
            float v3 = acc[i][j].w + b1;
            size_t i0 = (size_t)row * NK + col;
            size_t i1 = (size_t)(row + 8) * NK + col;
            if (EPI == 1) {
                v0 = 1.0f / (1.0f + expf(-v0));
                v1 = 1.0f / (1.0f + expf(-v1));
                v2 = 1.0f / (1.0f + expf(-v2));
                v3 = 1.0f / (1.0f + expf(-v3));
            } else if (EPI == 2) {
                float2 p0 = *reinterpret_cast<const float2*>(&add1[i0]);
                float2 p1 = *reinterpret_cast<const float2*>(&add1[i1]);
                float2 q0 = *reinterpret_cast<const float2*>(&add2[i0]);
                float2 q1 = *reinterpret_cast<const float2*>(&add2[i1]);
                v0 += p0.x + q0.x; v1 += p0.y + q0.y;
                v2 += p1.x + q1.x; v3 += p1.y + q1.y;
            }
            if (ROUND) {
                v0 = to_tf32(v0); v1 = to_tf32(v1);
                v2 = to_tf32(v2); v3 = to_tf32(v3);
            }
            *reinterpret_cast<float2*>(&C[i0]) = make_float2(v0, v1);
            *reinterpret_cast<float2*>(&C[i1]) = make_float2(v2, v3);
        }
    }
}

// ---------------- launch ----------------
extern "C" void kernel_launch(void* const* d_in, const int* in_sizes, int n_in,
                              void* d_out, int out_size) {
    (void)in_sizes; (void)n_in; (void)out_size;
    const float* x       = (const float*)d_in[0];
    const float* a_fwd   = (const float*)d_in[1];
    const float* Wf1     = (const float*)d_in[2];
    const float* bf1     = (const float*)d_in[3];
    const float* Wf2     = (const float*)d_in[4];
    const float* bf2     = (const float*)d_in[5];
    const float* Wbx     = (const float*)d_in[6];
    const float* bbx     = (const float*)d_in[7];
    const float* Wgx     = (const float*)d_in[8];
    const float* bgx     = (const float*)d_in[9];
    const float* Wga     = (const float*)d_in[10];
    const float* bga     = (const float*)d_in[11];
    const float* a_param = (const float*)d_in[12];
    const float* Wb2     = (const float*)d_in[13];
    const float* bb2     = (const float*)d_in[14];
    float* out = (float*)d_out;

    float *xg, *u, *v, *gx, *ga, *of, *wt, *endv, *Pv, *cr;
    cudaGetSymbolAddress((void**)&xg, g_xg);
    cudaGetSymbolAddress((void**)&u,  g_u);
    cudaGetSymbolAddress((void**)&v,  g_v);
    cudaGetSymbolAddress((void**)&gx, g_gx);
    cudaGetSymbolAddress((void**)&ga, g_ga);
    cudaGetSymbolAddress((void**)&of, g_of);
    cudaGetSymbolAddress((void**)&wt, g_wt);
    cudaGetSymbolAddress((void**)&endv, g_end);
    cudaGetSymbolAddress((void**)&Pv,  g_P);
    cudaGetSymbolAddress((void**)&cr,  g_cr);

    cudaFuncSetAttribute(gemm_kernel<0,0>, cudaFuncAttributeMaxDynamicSharedMemorySize, SMEM_REQ);
    cudaFuncSetAttribute(gemm_kernel<0,1>, cudaFuncAttributeMaxDynamicSharedMemorySize, SMEM_REQ);
    cudaFuncSetAttribute(gemm_kernel<1,0>, cudaFuncAttributeMaxDynamicSharedMemorySize, SMEM_REQ);
    cudaFuncSetAttribute(gemm_kernel<2,0>, cudaFuncAttributeMaxDynamicSharedMemorySize, SMEM_REQ);

    dim3 tb(32, 8), tg(32, 32);
    transround_kernel<<<tg, tb>>>(Wf1, wt + 0ull * NK * NK);
    transround_kernel<<<tg, tb>>>(Wbx, wt + 1ull * NK * NK);
    transround_kernel<<<tg, tb>>>(Wgx, wt + 2ull * NK * NK);
    transround_kernel<<<tg, tb>>>(Wga, wt + 3ull * NK * NK);
    transround_kernel<<<tg, tb>>>(Wf2, wt + 4ull * NK * NK);
    transround_kernel<<<tg, tb>>>(Wb2, wt + 5ull * NK * NK);

    const int EW_BLOCKS = (NELEM / 4) / 256;
    gelu_kernel<<<EW_BLOCKS, 256>>>(x, xg);

    dim3 ggrid(NK / TN, MTOT / TM);   // (8, 256)
    gemm_kernel<0,0><<<ggrid, 256, SMEM_REQ>>>(xg, wt + 0ull*NK*NK, bf1, u,  nullptr, nullptr);
    gemm_kernel<0,1><<<ggrid, 256, SMEM_REQ>>>(xg, wt + 1ull*NK*NK, bbx, v,  nullptr, nullptr);
    gemm_kernel<1,0><<<ggrid, 256, SMEM_REQ>>>(v,  wt + 2ull*NK*NK, bgx, gx, nullptr, nullptr);
    gemm_kernel<1,0><<<ggrid, 256, SMEM_REQ>>>(v,  wt + 3ull*NK*NK, bga, ga, nullptr, nullptr);

    gates_kernel<<<EW_BLOCKS, 256>>>(v, gx, ga, a_param);

    fwd_p1<<<BB * NCH, DD>>>(u, a_fwd, endv, Pv);
    fwd_p2<<<BB, DD>>>(endv, Pv, cr);
    fwd_p3<<<BB * NCH, DD>>>(u, a_fwd, cr);

    bwd_p1<<<BB * NCH, DD>>>(gx, ga, endv, Pv);
    bwd_p2<<<BB, DD>>>(endv, Pv, cr);
    bwd_p3<<<BB * NCH, DD>>>(gx, ga, cr);

    gemm_kernel<0,0><<<ggrid, 256, SMEM_REQ>>>(u,  wt + 4ull*NK*NK, bf2, of, nullptr, nullptr);
    gemm_kernel<2,0><<<ggrid, 256, SMEM_REQ>>>(gx, wt + 5ull*NK*NK, bb2, out, of, x);
}

// round 7
// speedup vs baseline: 1.0520x; 1.0520x over previous
#include <cuda_runtime.h>
#include <cstdint>

#define BB 8
#define SS 4096
#define DD 1024
#define MTOT (BB*SS)            // 32768
#define NELEM (MTOT*DD)
#define NK 1024

#define NCH 32
#define CHL 128                 // SS/NCH

// ---- GEMM tiling ----
#define TM 128
#define TN 128
#define TKC 32
#define KT (NK/TKC)             // 32
#define STAGES 3
#define AST 36                  // A smem row stride (floats)
#define BST 136                 // B smem row stride (floats)
#define ABYT (TM*AST*4)         // 18432
#define BBYT (TKC*BST*4)        // 17408
#define STBYT (ABYT+BBYT)       // 35840
#define SMEM_REQ (STAGES*STBYT) // 107520

// ---------------- scratch ----------------
__device__ float g_xg[NELEM];
__device__ float g_u [NELEM];
__device__ float g_v [NELEM];
__device__ float g_gx[NELEM];
__device__ float g_ga[NELEM];
__device__ float g_of[NELEM];
__device__ float g_wt[6*NK*NK];          // tf32-rounded weights [K][N]
__device__ float g_sp[DD];               // softplus(a_param)
__device__ float g_end[BB*NCH*DD];
__device__ float g_P  [BB*NCH*DD];
__device__ float g_cr [BB*NCH*DD];

// ---------------- helpers ----------------
__device__ __forceinline__ float to_tf32(float x) {
    float r; asm("cvt.rna.tf32.f32 %0, %1;" : "=f"(r) : "f"(x)); return r;
}
__device__ __forceinline__ uint32_t smem_u32(const void* p) {
    uint32_t a;
    asm("{ .reg .u64 t; cvta.to.shared.u64 t, %1; cvt.u32.u64 %0, t; }" : "=r"(a) : "l"(p));
    return a;
}
__device__ __forceinline__ void cp16(uint32_t saddr, const void* gaddr) {
    asm volatile("cp.async.cg.shared.global [%0], [%1], 16;" :: "r"(saddr), "l"(gaddr));
}
__device__ __forceinline__ void cp_commit() {
    asm volatile("cp.async.commit_group;" ::: "memory");
}
__device__ __forceinline__ void cp_wait1() {
    asm volatile("cp.async.wait_group 1;" ::: "memory");
}
__device__ __forceinline__ void mma_tf32(float4& c, const uint32_t* a, const uint32_t* b) {
    asm volatile(
        "mma.sync.aligned.m16n8k8.row.col.f32.tf32.tf32.f32 "
        "{%0,%1,%2,%3},{%4,%5,%6,%7},{%8,%9},{%0,%1,%2,%3};\n"
        : "+f"(c.x), "+f"(c.y), "+f"(c.z), "+f"(c.w)
        : "r"(a[0]), "r"(a[1]), "r"(a[2]), "r"(a[3]), "r"(b[0]), "r"(b[1]));
}
__device__ __forceinline__ float fast_sigmoid(float x) {
    return 1.0f / (1.0f + __expf(-x));
}

// ---------------- weight prep: round all 6 to tf32, one launch ----------------
__global__ void roundw_all(const float* __restrict__ w0, const float* __restrict__ w1,
                           const float* __restrict__ w2, const float* __restrict__ w3,
                           const float* __restrict__ w4, const float* __restrict__ w5,
                           float* __restrict__ dst) {
    const float* srcs[6] = {w0, w1, w2, w3, w4, w5};
    int wsel = blockIdx.y;
    const float* src = srcs[wsel];
    float* d = dst + (size_t)wsel * NK * NK;
    int i = blockIdx.x * blockDim.x + threadIdx.x;
    float4 v = reinterpret_cast<const float4*>(src)[i];
    v.x = to_tf32(v.x); v.y = to_tf32(v.y); v.z = to_tf32(v.z); v.w = to_tf32(v.w);
    reinterpret_cast<float4*>(d)[i] = v;
}

// ---------------- softplus(a_param) precompute ----------------
__global__ void softplus_prep(const float* __restrict__ ap, float* __restrict__ sp) {
    int d = threadIdx.x;
    sp[d] = log1pf(expf(ap[d]));
}

// ---------------- gelu: x * sigmoid(2*inner) == 0.5x(1+tanh(inner)) ----------------
__global__ void gelu_kernel(const float* __restrict__ x, float* __restrict__ y) {
    int i = blockIdx.x * blockDim.x + threadIdx.x;
    float4 v = reinterpret_cast<const float4*>(x)[i];
    float* p = &v.x;
    float4 r; float* q = &r.x;
#pragma unroll
    for (int k = 0; k < 4; ++k) {
        float t = p[k];
        float inner = 0.7978845608028654f * (t + 0.044715f * t * t * t);
        q[k] = to_tf32(t * fast_sigmoid(2.0f * inner));
    }
    reinterpret_cast<float4*>(y)[i] = r;
}

// ---------------- RG-LRU gate math (softplus precomputed) ----------------
__global__ void gates_kernel(const float* __restrict__ v,
                             float* __restrict__ gx,
                             float* __restrict__ ga,
                             const float* __restrict__ sp) {
    int i = blockIdx.x * blockDim.x + threadIdx.x;
    int d0 = (i * 4) & (DD - 1);
    float4 vv  = reinterpret_cast<const float4*>(v)[i];
    float4 gxx = reinterpret_cast<float4*>(gx)[i];
    float4 gaa = reinterpret_cast<float4*>(ga)[i];
    float4 spv = *reinterpret_cast<const float4*>(&sp[d0]);
    const float* pv = &vv.x; const float* pgx = &gxx.x;
    const float* pga = &gaa.x; const float* psp = &spv.x;
    float4 oa, os; float* pa = &oa.x; float* ps = &os.x;
#pragma unroll
    for (int k = 0; k < 4; ++k) {
        float la = -8.0f * pga[k] * psp[k];
        pa[k] = expf(la);
        ps[k] = sqrtf(1.0f - expf(2.0f * la)) * pgx[k] * pv[k];
    }
    reinterpret_cast<float4*>(ga)[i] = oa;
    reinterpret_cast<float4*>(gx)[i] = os;
}

// ---------------- chunked scans (3-pass) ----------------
__global__ void fwd_p1(const float* __restrict__ u, const float* __restrict__ a_fwd,
                       float* __restrict__ endv, float* __restrict__ Pv) {
    int d = threadIdx.x, bc = blockIdx.x;
    float a = a_fwd[d];
    size_t base = (size_t)bc * CHL * DD + d;
    float h = 0.f;
#pragma unroll 4
    for (int t = 0; t < CHL; ++t) h = fmaf(a, h, u[base + (size_t)t * DD]);
    float p = a;
#pragma unroll
    for (int i = 0; i < 7; ++i) p *= p;   // a^128
    endv[bc * DD + d] = h; Pv[bc * DD + d] = p;
}

__global__ void fwd_p2(const float* __restrict__ endv, const float* __restrict__ Pv,
                       float* __restrict__ cr) {
    int g = blockIdx.x * blockDim.x + threadIdx.x;
    int b = g >> 10, d = g & 1023;
    float acc = 0.f;
    for (int c = 0; c < NCH; ++c) {
        size_t i = (size_t)(b * NCH + c) * DD + d;
        cr[i] = acc;
        acc = endv[i] + Pv[i] * acc;
    }
}

__global__ void fwd_p3(float* __restrict__ u, const float* __restrict__ a_fwd,
                       const float* __restrict__ cr) {
    int d = threadIdx.x, bc = blockIdx.x;
    float a = a_fwd[d];
    size_t base = (size_t)bc * CHL * DD + d;
    float h = cr[bc * DD + d];
#pragma unroll 4
    for (int t = 0; t < CHL; ++t) {
        size_t i = base + (size_t)t * DD;
        h = fmaf(a, h, u[i]);
        u[i] = to_tf32(h);
    }
}

__global__ void bwd_p1(const float* __restrict__ s, const float* __restrict__ a,
                       float* __restrict__ endv, float* __restrict__ Pv) {
    int d = threadIdx.x, bc = blockIdx.x;
    size_t base = (size_t)bc * CHL * DD + d;
    float h = 0.f, p = 1.f;
#pragma unroll 4
    for (int t = CHL - 1; t >= 0; --t) {
        size_t i = base + (size_t)t * DD;
        float av = a[i];
        h = fmaf(av, h, s[i]);
        p *= av;
    }
    endv[bc * DD + d] = h; Pv[bc * DD + d] = p;
}

__global__ void bwd_p2(const float* __restrict__ endv, const float* __restrict__ Pv,
                       float* __restrict__ cr) {
    int g = blockIdx.x * blockDim.x + threadIdx.x;
    int b = g >> 10, d = g & 1023;
    float acc = 0.f;
    for (int c = NCH - 1; c >= 0; --c) {
        size_t i = (size_t)(b * NCH + c) * DD + d;
        cr[i] = acc;
        acc = endv[i] + Pv[i] * acc;
    }
}

__global__ void bwd_p3(float* __restrict__ s, const float* __restrict__ a,
                       const float* __restrict__ cr) {
    int d = threadIdx.x, bc = blockIdx.x;
    size_t base = (size_t)bc * CHL * DD + d;
    float h = cr[bc * DD + d];
#pragma unroll 4
    for (int t = CHL - 1; t >= 0; --t) {
        size_t i = base + (size_t)t * DD;
        h = fmaf(a[i], h, s[i]);
        s[i] = to_tf32(h);
    }
}

// ---------------- GEMM: C[M,N] = A[M,K] @ W[K,N] + bias ----------------
// Operands pre-rounded to tf32. Single barrier per k-tile.
// EPI: 0 = bias, 1 = sigmoid(acc+bias), 2 = acc+bias+add1+add2; ROUND: tf32 out
template <int EPI, int ROUND>
__global__ __launch_bounds__(256, 2)
void gemm_kernel(const float* __restrict__ A, const float* __restrict__ W,
                 const float* __restrict__ bias, float* __restrict__ C,
                 const float* __restrict__ add1, const float* __restrict__ add2) {
    extern __shared__ char sm[];
    const uint32_t smb = smem_u32(sm);

    const int tid  = threadIdx.x;
    const int wid  = tid >> 5;
    const int lane = tid & 31;
    const int wm   = wid & 3;
    const int wn   = wid >> 2;
    const int g    = lane >> 2;
    const int tg   = lane & 3;
    const int bm   = blockIdx.y;
    const int bn   = blockIdx.x;

    const float* Abase = A + (size_t)(bm * TM) * NK;
    const float* Wbase = W + bn * TN;

    uint32_t sA[4], sB[4];
    const float* gA[4]; const float* gB[4];
#pragma unroll
    for (int it = 0; it < 4; ++it) {
        int p = tid + it * 256;
        int arow = p >> 3, acol = p & 7;          // A[128][8 float4]
        int brow = p >> 5, bcol = p & 31;         // B[32][32 float4]
        sA[it] = (uint32_t)((arow * AST + acol * 4) * 4);
        sB[it] = (uint32_t)(ABYT + (brow * BST + bcol * 4) * 4);
        gA[it] = Abase + (size_t)arow * NK + acol * 4;
        gB[it] = Wbase + (size_t)brow * NK + bcol * 4;
    }

    auto issue = [&](int kt) {
        const uint32_t sb = smb + (kt % STAGES) * STBYT;
        const int ko = kt * TKC;
        const size_t bo = (size_t)kt * TKC * NK;
#pragma unroll
        for (int it = 0; it < 4; ++it) cp16(sb + sA[it], gA[it] + ko);
#pragma unroll
        for (int it = 0; it < 4; ++it) cp16(sb + sB[it], gB[it] + bo);
    };

    float4 acc[2][8];
#pragma unroll
    for (int i = 0; i < 2; ++i)
#pragma unroll
        for (int j = 0; j < 8; ++j) acc[i][j] = make_float4(0.f, 0.f, 0.f, 0.f);

    issue(0); cp_commit();
    issue(1); cp_commit();

    const int arow0 = wm * 32 + g;
    const int ncol0 = wn * 64 + g;

    for (int kt = 0; kt < KT; ++kt) {
        cp_wait1();
        __syncthreads();                         // single barrier per k-tile
        if (kt + 2 < KT) issue(kt + 2);
        cp_commit();

        const float* As0 = (const float*)(sm + (kt % STAGES) * STBYT);
        const float* Bs0 = As0 + TM * AST;
        const float* aR = As0 + arow0 * AST + tg;
        const float* bR = Bs0 + tg * BST + ncol0;

#pragma unroll
        for (int kk = 0; kk < TKC; kk += 8) {
            uint32_t af[2][4], bf[8][2];
#pragma unroll
            for (int i = 0; i < 2; ++i) {
                const float* a0 = aR + i * 16 * AST + kk;
                af[i][0] = __float_as_uint(a0[0]);
                af[i][1] = __float_as_uint(a0[8 * AST]);
                af[i][2] = __float_as_uint(a0[4]);
                af[i][3] = __float_as_uint(a0[8 * AST + 4]);
            }
#pragma unroll
            for (int j = 0; j < 8; ++j) {
                const float* b0 = bR + kk * BST + j * 8;
                bf[j][0] = __float_as_uint(b0[0]);
                bf[j][1] = __float_as_uint(b0[4 * BST]);
            }
#pragma unroll
            for (int i = 0; i < 2; ++i)
#pragma unroll
                for (int j = 0; j < 8; ++j) mma_tf32(acc[i][j], af[i], bf[j]);
        }
    }

    // epilogue
#pragma unroll
    for (int i = 0; i < 2; ++i) {
        int row = bm * TM + wm * 32 + i * 16 + g;
#pragma unroll
        for (int j = 0; j < 8; ++j) {
            int col = bn * TN + wn * 64 + j * 8 + tg * 2;
            float b0 = bias[col], b1 = bias[col + 1];
            float v0 = acc[i][j].x + b0;
            float v1 = acc[i][j].y + b1;
            float v2 = acc[i][j].z + b0;
            float v3 = acc[i][j].w + b1;
            size_t i0 = (size_t)row * NK + col;
            size_t i1 = (size_t)(row + 8) * NK + col;
            if (EPI == 1) {
                v0 = fast_sigmoid(v0);
                v1 = fast_sigmoid(v1);
                v2 = fast_sigmoid(v2);
                v3 = fast_sigmoid(v3);
            } else if (EPI == 2) {
                float2 p0 = *reinterpret_cast<const float2*>(&add1[i0]);
                float2 p1 = *reinterpret_cast<const float2*>(&add1[i1]);
                float2 q0 = *reinterpret_cast<const float2*>(&add2[i0]);
                float2 q1 = *reinterpret_cast<const float2*>(&add2[i1]);
                v0 += p0.x + q0.x; v1 += p0.y + q0.y;
                v2 += p1.x + q1.x; v3 += p1.y + q1.y;
            }
            if (ROUND) {
                v0 = to_tf32(v0); v1 = to_tf32(v1);
                v2 = to_tf32(v2); v3 = to_tf32(v3);
            }
            *reinterpret_cast<float2*>(&C[i0]) = make_float2(v0, v1);
            *reinterpret_cast<float2*>(&C[i1]) = make_float2(v2, v3);
        }
    }
}

// ---------------- launch ----------------
extern "C" void kernel_launch(void* const* d_in, const int* in_sizes, int n_in,
                              void* d_out, int out_size) {
    (void)in_sizes; (void)n_in; (void)out_size;
    const float* x       = (const float*)d_in[0];
    const float* a_fwd   = (const float*)d_in[1];
    const float* Wf1     = (const float*)d_in[2];
    const float* bf1     = (const float*)d_in[3];
    const float* Wf2     = (const float*)d_in[4];
    const float* bf2     = (const float*)d_in[5];
    const float* Wbx     = (const float*)d_in[6];
    const float* bbx     = (const float*)d_in[7];
    const float* Wgx     = (const float*)d_in[8];
    const float* bgx     = (const float*)d_in[9];
    const float* Wga     = (const float*)d_in[10];
    const float* bga     = (const float*)d_in[11];
    const float* a_param = (const float*)d_in[12];
    const float* Wb2     = (const float*)d_in[13];
    const float* bb2     = (const float*)d_in[14];
    float* out = (float*)d_out;

    float *xg, *u, *v, *gx, *ga, *of, *wt, *sp, *endv, *Pv, *cr;
    cudaGetSymbolAddress((void**)&xg, g_xg);
    cudaGetSymbolAddress((void**)&u,  g_u);
    cudaGetSymbolAddress((void**)&v,  g_v);
    cudaGetSymbolAddress((void**)&gx, g_gx);
    cudaGetSymbolAddress((void**)&ga, g_ga);
    cudaGetSymbolAddress((void**)&of, g_of);
    cudaGetSymbolAddress((void**)&wt, g_wt);
    cudaGetSymbolAddress((void**)&sp, g_sp);
    cudaGetSymbolAddress((void**)&endv, g_end);
    cudaGetSymbolAddress((void**)&Pv,  g_P);
    cudaGetSymbolAddress((void**)&cr,  g_cr);

    cudaFuncSetAttribute(gemm_kernel<0,0>, cudaFuncAttributeMaxDynamicSharedMemorySize, SMEM_REQ);
    cudaFuncSetAttribute(gemm_kernel<0,1>, cudaFuncAttributeMaxDynamicSharedMemorySize, SMEM_REQ);
    cudaFuncSetAttribute(gemm_kernel<1,0>, cudaFuncAttributeMaxDynamicSharedMemorySize, SMEM_REQ);
    cudaFuncSetAttribute(gemm_kernel<2,0>, cudaFuncAttributeMaxDynamicSharedMemorySize, SMEM_REQ);

    // launch 1: all weight rounding in one kernel
    dim3 rwgrid(NK * NK / 4 / 256, 6);
    roundw_all<<<rwgrid, 256>>>(Wf1, Wbx, Wgx, Wga, Wf2, Wb2, wt);
    // launch 2
    softplus_prep<<<1, DD>>>(a_param, sp);

    const int EW_BLOCKS = (NELEM / 4) / 256;
    // launch 3
    gelu_kernel<<<EW_BLOCKS, 256>>>(x, xg);

    dim3 ggrid(NK / TN, MTOT / TM);   // (8, 256)
    // launches 4,5,6 (ncu -s 5 -c 1 profiles launch 6 = gate_x GEMM)
    gemm_kernel<0,0><<<ggrid, 256, SMEM_REQ>>>(xg, wt + 0ull*NK*NK, bf1, u,  nullptr, nullptr);
    gemm_kernel<0,1><<<ggrid, 256, SMEM_REQ>>>(xg, wt + 1ull*NK*NK, bbx, v,  nullptr, nullptr);
    gemm_kernel<1,0><<<ggrid, 256, SMEM_REQ>>>(v,  wt + 2ull*NK*NK, bgx, gx, nullptr, nullptr);
    gemm_kernel<1,0><<<ggrid, 256, SMEM_REQ>>>(v,  wt + 3ull*NK*NK, bga, ga, nullptr, nullptr);

    gates_kernel<<<EW_BLOCKS, 256>>>(v, gx, ga, sp);

    fwd_p1<<<BB * NCH, DD>>>(u, a_fwd, endv, Pv);
    fwd_p2<<<BB, DD>>>(endv, Pv, cr);
    fwd_p3<<<BB * NCH, DD>>>(u, a_fwd, cr);

    bwd_p1<<<BB * NCH, DD>>>(gx, ga, endv, Pv);
    bwd_p2<<<BB, DD>>>(endv, Pv, cr);
    bwd_p3<<<BB * NCH, DD>>>(gx, ga, cr);

    gemm_kernel<0,0><<<ggrid, 256, SMEM_REQ>>>(u,  wt + 4ull*NK*NK, bf2, of, nullptr, nullptr);
    gemm_kernel<2,0><<<ggrid, 256, SMEM_REQ>>>(gx, wt + 5ull*NK*NK, bb2, out, of, x);
}